// round 2
// baseline (speedup 1.0000x reference)
#include <cuda_runtime.h>

// Scratch: K projection (B*L x D) and attention output (B*L x D), fp32.
__device__ float g_K[4096 * 1024];
__device__ float g_att[4096 * 1024];

__device__ __forceinline__ float fast_exp2(float x) {
    float y;
    asm("ex2.approx.ftz.f32 %0, %1;" : "=f"(y) : "f"(x));
    return y;
}

// ---------------------------------------------------------------------------
// Tiled SGEMM: C[M,N] = A[M,1024] @ B[1024,N] + bias[N]
//   A row-major lda=1024, B row-major with ldb (3072 for W_attn slice, 1024
//   for W_proj), C row-major ldc=1024. BM=BN=64, BK=16, 256 threads,
//   4x4 accumulators per thread with strided (q, q+16, q+32, q+48) mapping so
//   As/Bs reads are broadcast / conflict-free with stride-65 padding.
// ---------------------------------------------------------------------------
__global__ __launch_bounds__(256) void gemm_kernel(
    const float* __restrict__ A, const float* __restrict__ B,
    const float* __restrict__ bias, float* __restrict__ C,
    int ldb)
{
    __shared__ float As[16 * 65];  // As[k][m], padded
    __shared__ float Bs[16 * 65];  // Bs[k][n], padded

    const int tid = threadIdx.x;
    const int tx = tid & 15;
    const int ty = tid >> 4;
    const int n0 = blockIdx.x * 64;
    const int m0 = blockIdx.y * 64;

    float acc[4][4];
#pragma unroll
    for (int i = 0; i < 4; i++)
#pragma unroll
        for (int j = 0; j < 4; j++) acc[i][j] = 0.0f;

    for (int kt = 0; kt < 1024; kt += 16) {
        // Load A tile 64x16 transposed into As[k][m]
#pragma unroll
        for (int p = 0; p < 4; p++) {
            int m = (tid >> 4) + p * 16;
            int k = tid & 15;
            As[k * 65 + m] = A[(m0 + m) * 1024 + kt + k];
        }
        // Load B tile 16x64 into Bs[k][n]
#pragma unroll
        for (int p = 0; p < 4; p++) {
            int k = (tid >> 6) + p * 4;
            int n = tid & 63;
            Bs[k * 65 + n] = B[(kt + k) * ldb + n0 + n];
        }
        __syncthreads();

#pragma unroll
        for (int k = 0; k < 16; k++) {
            float a[4], b[4];
#pragma unroll
            for (int i = 0; i < 4; i++) a[i] = As[k * 65 + ty + 16 * i];
#pragma unroll
            for (int j = 0; j < 4; j++) b[j] = Bs[k * 65 + tx + 16 * j];
#pragma unroll
            for (int i = 0; i < 4; i++)
#pragma unroll
                for (int j = 0; j < 4; j++) acc[i][j] = fmaf(a[i], b[j], acc[i][j]);
        }
        __syncthreads();
    }

#pragma unroll
    for (int j = 0; j < 4; j++) {
        int n = n0 + tx + 16 * j;
        float bv = bias[n];
#pragma unroll
        for (int i = 0; i < 4; i++) {
            int m = m0 + ty + 16 * i;
            C[m * 1024 + n] = acc[i][j] + bv;
        }
    }
}

// ---------------------------------------------------------------------------
// Fused flash attention over K (Q == K here): per (b, h), 64-query blocks,
// 64-key tiles, online softmax, fp32.
//   K layout: g_K[(b*2048 + l)*1024 + h*64 + d]
//   Out written directly in (B, L, H*Dh) layout for the proj GEMM.
// ---------------------------------------------------------------------------
__global__ __launch_bounds__(256) void attn_kernel(
    const float* __restrict__ K, float* __restrict__ Out)
{
    extern __shared__ float sm[];
    float* Qt = sm;                 // [64][65]  Qt[d][q] (pre-scaled)
    float* Kt = sm + 64 * 65;       // [64][65]  Kt[d][j]
    float* Kn = sm + 2 * 64 * 65;   // [64][65]  Kn[j][d]
    float* Pt = sm + 3 * 64 * 65;   // [64][65]  Pt[j][q]

    const int tid = threadIdx.x;
    const int tx = tid & 15;
    const int ty = tid >> 4;
    const int b = blockIdx.y >> 4;
    const int h = blockIdx.y & 15;
    const int q0 = blockIdx.x * 64;

    const float* Kb = K + (size_t)b * 2048 * 1024 + h * 64;

    // scale = 1/sqrt(64) folded with log2(e) so softmax uses exp2
    const float QSCALE = 0.125f * 1.4426950408889634f;

    // Load Q tile transposed (coalesced global, conflict-free smem).
#pragma unroll
    for (int p = 0; p < 16; p++) {
        int i = tid + p * 256;
        int q = i >> 6, d = i & 63;
        Qt[d * 65 + q] = Kb[(q0 + q) * 1024 + d] * QSCALE;
    }

    float m_i[4], l_i[4], Oacc[4][4];
#pragma unroll
    for (int i = 0; i < 4; i++) {
        m_i[i] = -1e30f;
        l_i[i] = 0.0f;
#pragma unroll
        for (int d = 0; d < 4; d++) Oacc[i][d] = 0.0f;
    }

    for (int k0 = 0; k0 < 2048; k0 += 64) {
        __syncthreads();  // previous iteration done with Kn/Kt/Pt
        // Load K tile in both layouts (single global read).
#pragma unroll
        for (int p = 0; p < 16; p++) {
            int i = tid + p * 256;
            int j = i >> 6, d = i & 63;
            float v = Kb[(k0 + j) * 1024 + d];
            Kn[j * 65 + d] = v;
            Kt[d * 65 + j] = v;
        }
        __syncthreads();

        // S tile: s[i][j] = sum_d Qt[d][q] * Kt[d][k]
        float s[4][4];
#pragma unroll
        for (int i = 0; i < 4; i++)
#pragma unroll
            for (int j = 0; j < 4; j++) s[i][j] = 0.0f;

#pragma unroll 8
        for (int d = 0; d < 64; d++) {
            float a[4], bb[4];
#pragma unroll
            for (int i = 0; i < 4; i++) a[i] = Qt[d * 65 + ty + 16 * i];
#pragma unroll
            for (int j = 0; j < 4; j++) bb[j] = Kt[d * 65 + tx + 16 * j];
#pragma unroll
            for (int i = 0; i < 4; i++)
#pragma unroll
                for (int j = 0; j < 4; j++) s[i][j] = fmaf(a[i], bb[j], s[i][j]);
        }

        // Online softmax per query row (row spread over 16 lanes).
#pragma unroll
        for (int i = 0; i < 4; i++) {
            float mx = fmaxf(fmaxf(s[i][0], s[i][1]), fmaxf(s[i][2], s[i][3]));
            mx = fmaxf(mx, __shfl_xor_sync(0xffffffffu, mx, 1));
            mx = fmaxf(mx, __shfl_xor_sync(0xffffffffu, mx, 2));
            mx = fmaxf(mx, __shfl_xor_sync(0xffffffffu, mx, 4));
            mx = fmaxf(mx, __shfl_xor_sync(0xffffffffu, mx, 8));
            float mnew = fmaxf(m_i[i], mx);
            float corr = fast_exp2(m_i[i] - mnew);
            float rs = 0.0f;
#pragma unroll
            for (int j = 0; j < 4; j++) {
                s[i][j] = fast_exp2(s[i][j] - mnew);
                rs += s[i][j];
            }
            rs += __shfl_xor_sync(0xffffffffu, rs, 1);
            rs += __shfl_xor_sync(0xffffffffu, rs, 2);
            rs += __shfl_xor_sync(0xffffffffu, rs, 4);
            rs += __shfl_xor_sync(0xffffffffu, rs, 8);
            l_i[i] = l_i[i] * corr + rs;
            m_i[i] = mnew;
#pragma unroll
            for (int d = 0; d < 4; d++) Oacc[i][d] *= corr;
            // Stage P transposed for the AV GEMM.
#pragma unroll
            for (int j = 0; j < 4; j++)
                Pt[(tx + 16 * j) * 65 + (ty + 16 * i)] = s[i][j];
        }
        __syncthreads();

        // O += P @ Ktile : Oacc[i][d] += Pt[j][q] * Kn[j][d]
#pragma unroll 8
        for (int j = 0; j < 64; j++) {
            float a[4], bb[4];
#pragma unroll
            for (int i = 0; i < 4; i++) a[i] = Pt[j * 65 + ty + 16 * i];
#pragma unroll
            for (int d = 0; d < 4; d++) bb[d] = Kn[j * 65 + tx + 16 * d];
#pragma unroll
            for (int i = 0; i < 4; i++)
#pragma unroll
                for (int d = 0; d < 4; d++) Oacc[i][d] = fmaf(a[i], bb[d], Oacc[i][d]);
        }
    }

    // Normalize and write in (B, L, D) layout.
#pragma unroll
    for (int i = 0; i < 4; i++) {
        float inv = 1.0f / l_i[i];
        int q = q0 + ty + 16 * i;
#pragma unroll
        for (int d = 0; d < 4; d++) {
            Out[((size_t)b * 2048 + q) * 1024 + h * 64 + tx + 16 * d] = Oacc[i][d] * inv;
        }
    }
}

extern "C" void kernel_launch(void* const* d_in, const int* in_sizes, int n_in,
                              void* d_out, int out_size) {
    const float* x      = (const float*)d_in[0];  // (2, 2048, 1024)
    const float* W_attn = (const float*)d_in[1];  // (1024, 3072)
    const float* b_attn = (const float*)d_in[2];  // (3072,)
    const float* W_proj = (const float*)d_in[3];  // (1024, 1024)
    const float* b_proj = (const float*)d_in[4];  // (1024,)
    float* out = (float*)d_out;                   // (2, 2048, 1024)

    float *gK, *gA;
    cudaGetSymbolAddress((void**)&gK, g_K);
    cudaGetSymbolAddress((void**)&gA, g_att);

    const int ATTN_SMEM = 4 * 64 * 65 * (int)sizeof(float);  // 66560 B
    cudaFuncSetAttribute(attn_kernel,
                         cudaFuncAttributeMaxDynamicSharedMemorySize, ATTN_SMEM);

    dim3 gemm_grid(1024 / 64, 4096 / 64);  // (N tiles, M tiles)

    // Stage 1: K = x @ W_attn[:, D:2D] + b_attn[D:2D]   (only K slice is used)
    gemm_kernel<<<gemm_grid, 256>>>(x, W_attn + 1024, b_attn + 1024, gK, 3072);

    // Stage 2: per-(b,h) softmax(K K^T / sqrt(Dh)) K, fused flash style.
    attn_kernel<<<dim3(2048 / 64, 32), 256, ATTN_SMEM>>>(gK, gA);

    // Stage 3: out = att @ W_proj + b_proj
    gemm_kernel<<<gemm_grid, 256>>>(gA, W_proj, b_proj, out, 1024);
}

// round 3
// speedup vs baseline: 1.2086x; 1.2086x over previous
#include <cuda_runtime.h>

// Scratch: K projection (B*L x D) and attention output (B*L x D), fp32.
__device__ float g_K[4096 * 1024];
__device__ float g_att[4096 * 1024];

typedef unsigned long long ull;

__device__ __forceinline__ float fast_exp2(float x) {
    float y;
    asm("ex2.approx.ftz.f32 %0, %1;" : "=f"(y) : "f"(x));
    return y;
}

__device__ __forceinline__ ull pack2(float x, float y) {
    ull r;
    asm("mov.b64 %0, {%1, %2};" : "=l"(r) : "f"(x), "f"(y));
    return r;
}
__device__ __forceinline__ float2 unpack2(ull v) {
    float2 r;
    asm("mov.b64 {%0, %1}, %2;" : "=f"(r.x), "=f"(r.y) : "l"(v));
    return r;
}
__device__ __forceinline__ ull fma2(ull a, ull b, ull c) {
    ull d;
    asm("fma.rn.f32x2 %0, %1, %2, %3;" : "=l"(d) : "l"(a), "l"(b), "l"(c));
    return d;
}
__device__ __forceinline__ ull mul2(ull a, ull b) {
    ull d;
    asm("mul.rn.f32x2 %0, %1, %2;" : "=l"(d) : "l"(a), "l"(b));
    return d;
}

// ---------------------------------------------------------------------------
// Packed-f32x2 SGEMM: C[M,N] = A[M,1024] @ B[1024,N] + bias[N]
//   Block tile 128(m) x 64(n), BK=16, 256 threads, per-thread 8x4.
//   As[m][k] and Bs[n][k]: reduction dim k contiguous -> LDS.64 operand pairs.
//   Pad rows to 18 floats (9 ull) for conflict-free 64-bit loads.
// ---------------------------------------------------------------------------
__global__ __launch_bounds__(256) void gemm_kernel(
    const float* __restrict__ A, const float* __restrict__ B,
    const float* __restrict__ bias, float* __restrict__ C,
    int ldb)
{
    __shared__ float As[128 * 18];  // As[m][k]
    __shared__ float Bs[64 * 18];   // Bs[n][k]
    const ull* As64 = (const ull*)As;
    const ull* Bs64 = (const ull*)Bs;

    const int tid = threadIdx.x;
    const int tx = tid & 15;
    const int ty = tid >> 4;
    const int n0 = blockIdx.x * 64;
    const int m0 = blockIdx.y * 128;

    ull acc[8][4];
#pragma unroll
    for (int i = 0; i < 8; i++)
#pragma unroll
        for (int j = 0; j < 4; j++) acc[i][j] = 0ull;

    const int la_k = tid & 15, la_m = tid >> 4;     // A loader
    const int lb_n = tid & 63, lb_k = tid >> 6;     // B loader

    for (int kt = 0; kt < 1024; kt += 16) {
#pragma unroll
        for (int p = 0; p < 8; p++) {
            int m = la_m + 16 * p;
            As[m * 18 + la_k] = A[(size_t)(m0 + m) * 1024 + kt + la_k];
        }
#pragma unroll
        for (int p = 0; p < 4; p++) {
            int k = lb_k + 4 * p;
            Bs[lb_n * 18 + k] = B[(size_t)(kt + k) * ldb + n0 + lb_n];
        }
        __syncthreads();

#pragma unroll
        for (int kk = 0; kk < 8; kk++) {
            ull a[8], b[4];
#pragma unroll
            for (int i = 0; i < 8; i++) a[i] = As64[(ty + 16 * i) * 9 + kk];
#pragma unroll
            for (int j = 0; j < 4; j++) b[j] = Bs64[(tx + 16 * j) * 9 + kk];
#pragma unroll
            for (int i = 0; i < 8; i++)
#pragma unroll
                for (int j = 0; j < 4; j++) acc[i][j] = fma2(a[i], b[j], acc[i][j]);
        }
        __syncthreads();
    }

#pragma unroll
    for (int j = 0; j < 4; j++) {
        int n = n0 + tx + 16 * j;
        float bv = bias[n];
#pragma unroll
        for (int i = 0; i < 8; i++) {
            int m = m0 + ty + 16 * i;
            float2 v = unpack2(acc[i][j]);
            C[(size_t)m * 1024 + n] = v.x + v.y + bv;
        }
    }
}

// ---------------------------------------------------------------------------
// Fused flash attention over K (Q == K): per (b, h), 64-query blocks,
// 128-key tiles, online softmax, packed f32x2 FMAs.
//   Layouts (reduction dim contiguous):
//     Qt[q][d] (pad 66), Ks[j][d] (pad 66)  -> S GEMM pairs over d
//     Kd[d][j] (pad 130), Pt[q][j] (pad 130) -> AV GEMM pairs over j
// ---------------------------------------------------------------------------
__global__ __launch_bounds__(256) void attn_kernel(
    const float* __restrict__ K, float* __restrict__ Out)
{
    extern __shared__ float sm[];
    float* Qt = sm;                       // 64 * 66
    float* Ks = sm + 64 * 66;             // 128 * 66
    float* Kd = sm + 64 * 66 + 128 * 66;  // 64 * 130
    float* Pt = Kd + 64 * 130;            // 64 * 130
    const ull* Qt64 = (const ull*)Qt;
    const ull* Ks64 = (const ull*)Ks;
    const ull* Kd64 = (const ull*)Kd;
    const ull* Pt64 = (const ull*)Pt;

    const int tid = threadIdx.x;
    const int tx = tid & 15;
    const int ty = tid >> 4;
    const int b = blockIdx.y >> 4;
    const int h = blockIdx.y & 15;
    const int q0 = blockIdx.x * 64;

    const float* Kb = K + (size_t)b * 2048 * 1024 + h * 64;

    // scale = 1/sqrt(64) folded with log2(e) so softmax uses exp2
    const float QSCALE = 0.125f * 1.4426950408889634f;

    // Load Q tile: Qt[q][d], pre-scaled. Coalesced global.
#pragma unroll
    for (int p = 0; p < 16; p++) {
        int i = tid + p * 256;
        int q = i >> 6, d = i & 63;
        Qt[q * 66 + d] = Kb[(size_t)(q0 + q) * 1024 + d] * QSCALE;
    }

    float m_i[4], l_i[4];
    ull O2[4][4];
#pragma unroll
    for (int i = 0; i < 4; i++) {
        m_i[i] = -1e30f;
        l_i[i] = 0.0f;
#pragma unroll
        for (int d = 0; d < 4; d++) O2[i][d] = 0ull;
    }

    for (int k0 = 0; k0 < 2048; k0 += 128) {
        __syncthreads();  // previous iteration done with tiles
        // Load K tile (128 keys x 64 d) in both layouts, single global read.
#pragma unroll
        for (int p = 0; p < 32; p++) {
            int i = tid + p * 256;
            int j = i >> 6, d = i & 63;
            float v = Kb[(size_t)(k0 + j) * 1024 + d];
            Ks[j * 66 + d] = v;
            Kd[d * 130 + j] = v;
        }
        __syncthreads();

        // S tile: s2[i][j] += Qt[q][dpair] * Ks[k][dpair]
        ull s2[4][8];
#pragma unroll
        for (int i = 0; i < 4; i++)
#pragma unroll
            for (int j = 0; j < 8; j++) s2[i][j] = 0ull;

#pragma unroll 8
        for (int dd = 0; dd < 32; dd++) {
            ull a[4], bb[8];
#pragma unroll
            for (int i = 0; i < 4; i++) a[i] = Qt64[(ty + 16 * i) * 33 + dd];
#pragma unroll
            for (int j = 0; j < 8; j++) bb[j] = Ks64[(tx + 16 * j) * 33 + dd];
#pragma unroll
            for (int i = 0; i < 4; i++)
#pragma unroll
                for (int j = 0; j < 8; j++) s2[i][j] = fma2(a[i], bb[j], s2[i][j]);
        }

        // Online softmax per query row (row of 128 spread over 16 lanes x 8).
#pragma unroll
        for (int i = 0; i < 4; i++) {
            float s[8];
            float mx = -1e30f;
#pragma unroll
            for (int j = 0; j < 8; j++) {
                float2 v = unpack2(s2[i][j]);
                s[j] = v.x + v.y;
                mx = fmaxf(mx, s[j]);
            }
            mx = fmaxf(mx, __shfl_xor_sync(0xffffffffu, mx, 1));
            mx = fmaxf(mx, __shfl_xor_sync(0xffffffffu, mx, 2));
            mx = fmaxf(mx, __shfl_xor_sync(0xffffffffu, mx, 4));
            mx = fmaxf(mx, __shfl_xor_sync(0xffffffffu, mx, 8));
            float mnew = fmaxf(m_i[i], mx);
            float corr = fast_exp2(m_i[i] - mnew);
            float rs = 0.0f;
#pragma unroll
            for (int j = 0; j < 8; j++) {
                s[j] = fast_exp2(s[j] - mnew);
                rs += s[j];
            }
            rs += __shfl_xor_sync(0xffffffffu, rs, 1);
            rs += __shfl_xor_sync(0xffffffffu, rs, 2);
            rs += __shfl_xor_sync(0xffffffffu, rs, 4);
            rs += __shfl_xor_sync(0xffffffffu, rs, 8);
            l_i[i] = l_i[i] * corr + rs;
            m_i[i] = mnew;
            ull c2 = pack2(corr, corr);
#pragma unroll
            for (int d = 0; d < 4; d++) O2[i][d] = mul2(O2[i][d], c2);
            // Stage P in [q][j] layout for the AV GEMM (pairs over j).
            float* prow = Pt + (ty + 16 * i) * 130;
#pragma unroll
            for (int j = 0; j < 8; j++) prow[tx + 16 * j] = s[j];
        }
        __syncthreads();

        // O2[i][d] += Pt[q][jpair] * Kd[d][jpair]
#pragma unroll 8
        for (int jj = 0; jj < 64; jj++) {
            ull a[4], bb[4];
#pragma unroll
            for (int i = 0; i < 4; i++) a[i] = Pt64[(ty + 16 * i) * 65 + jj];
#pragma unroll
            for (int d = 0; d < 4; d++) bb[d] = Kd64[(tx + 16 * d) * 65 + jj];
#pragma unroll
            for (int i = 0; i < 4; i++)
#pragma unroll
                for (int d = 0; d < 4; d++) O2[i][d] = fma2(a[i], bb[d], O2[i][d]);
        }
    }

    // Normalize and write in (B, L, D) layout.
#pragma unroll
    for (int i = 0; i < 4; i++) {
        float inv = 1.0f / l_i[i];
        int q = q0 + ty + 16 * i;
#pragma unroll
        for (int d = 0; d < 4; d++) {
            float2 v = unpack2(O2[i][d]);
            Out[((size_t)b * 2048 + q) * 1024 + h * 64 + tx + 16 * d] = (v.x + v.y) * inv;
        }
    }
}

extern "C" void kernel_launch(void* const* d_in, const int* in_sizes, int n_in,
                              void* d_out, int out_size) {
    const float* x      = (const float*)d_in[0];  // (2, 2048, 1024)
    const float* W_attn = (const float*)d_in[1];  // (1024, 3072)
    const float* b_attn = (const float*)d_in[2];  // (3072,)
    const float* W_proj = (const float*)d_in[3];  // (1024, 1024)
    const float* b_proj = (const float*)d_in[4];  // (1024,)
    float* out = (float*)d_out;                   // (2, 2048, 1024)

    float *gK, *gA;
    cudaGetSymbolAddress((void**)&gK, g_K);
    cudaGetSymbolAddress((void**)&gA, g_att);

    const int ATTN_SMEM = (64 * 66 + 128 * 66 + 64 * 130 + 64 * 130) * (int)sizeof(float);  // 117248
    cudaFuncSetAttribute(attn_kernel,
                         cudaFuncAttributeMaxDynamicSharedMemorySize, ATTN_SMEM);

    dim3 gemm_grid(1024 / 64, 4096 / 128);  // (N tiles, M tiles)

    // Stage 1: K = x @ W_attn[:, D:2D] + b_attn[D:2D]   (only K slice is used)
    gemm_kernel<<<gemm_grid, 256>>>(x, W_attn + 1024, b_attn + 1024, gK, 3072);

    // Stage 2: per-(b,h) softmax(K K^T / sqrt(Dh)) K, fused flash style.
    attn_kernel<<<dim3(2048 / 64, 32), 256, ATTN_SMEM>>>(gK, gA);

    // Stage 3: out = att @ W_proj + b_proj
    gemm_kernel<<<gemm_grid, 256>>>(gA, W_proj, b_proj, out, 1024);
}

// round 5
// speedup vs baseline: 1.5216x; 1.2589x over previous
#include <cuda_runtime.h>
#include <cuda_bf16.h>
#include <cstdint>

typedef unsigned long long ull;

// ---------------- scratch (__device__ globals; no allocation allowed) -------
__device__ float g_K[4096 * 1024];                    // stage-1 output (fp32)
__device__ __nv_bfloat16 g_xs_hi[4096 * 1024];        // split of x
__device__ __nv_bfloat16 g_xs_lo[4096 * 1024];
__device__ __nv_bfloat16 g_att_hi[4096 * 1024];       // split of attention out
__device__ __nv_bfloat16 g_att_lo[4096 * 1024];
__device__ __nv_bfloat16 g_wk_hi[1024 * 1024];        // W_attn K-slice, [n][k]
__device__ __nv_bfloat16 g_wk_lo[1024 * 1024];
__device__ __nv_bfloat16 g_wp_hi[1024 * 1024];        // W_proj, [n][k]
__device__ __nv_bfloat16 g_wp_lo[1024 * 1024];

// ---------------- PTX helpers (all sm_80-compatible) -------------------------
__device__ __forceinline__ float fast_exp2(float x) {
    float y; asm("ex2.approx.ftz.f32 %0, %1;" : "=f"(y) : "f"(x)); return y;
}
__device__ __forceinline__ ull pack2(float x, float y) {
    ull r; asm("mov.b64 %0, {%1, %2};" : "=l"(r) : "f"(x), "f"(y)); return r;
}
__device__ __forceinline__ float2 unpack2(ull v) {
    float2 r; asm("mov.b64 {%0, %1}, %2;" : "=f"(r.x), "=f"(r.y) : "l"(v)); return r;
}
__device__ __forceinline__ ull fma2(ull a, ull b, ull c) {
    ull d; asm("fma.rn.f32x2 %0, %1, %2, %3;" : "=l"(d) : "l"(a), "l"(b), "l"(c)); return d;
}
__device__ __forceinline__ ull mul2(ull a, ull b) {
    ull d; asm("mul.rn.f32x2 %0, %1, %2;" : "=l"(d) : "l"(a), "l"(b)); return d;
}
__device__ __forceinline__ uint32_t smem_u32(const void* p) {
    uint32_t a;
    asm("{ .reg .u64 t; cvta.to.shared.u64 t, %1; cvt.u32.u64 %0, t; }" : "=r"(a) : "l"(p));
    return a;
}
__device__ __forceinline__ void cp_async16(uint32_t dst, const void* src) {
    asm volatile("cp.async.cg.shared.global [%0], [%1], 16;" :: "r"(dst), "l"(src));
}
__device__ __forceinline__ void cp_commit() {
    asm volatile("cp.async.commit_group;" ::: "memory");
}
__device__ __forceinline__ void cp_wait1() {
    asm volatile("cp.async.wait_group 1;" ::: "memory");
}
__device__ __forceinline__ void cp_wait0() {
    asm volatile("cp.async.wait_group 0;" ::: "memory");
}
__device__ __forceinline__ void ldsm4(uint32_t& r0, uint32_t& r1, uint32_t& r2,
                                      uint32_t& r3, uint32_t addr) {
    asm volatile("ldmatrix.sync.aligned.m8n8.x4.shared.b16 {%0,%1,%2,%3}, [%4];"
                 : "=r"(r0), "=r"(r1), "=r"(r2), "=r"(r3) : "r"(addr));
}
__device__ __forceinline__ void mma_bf16(float* c, const uint32_t* a,
                                         uint32_t b0, uint32_t b1) {
    asm volatile(
        "mma.sync.aligned.m16n8k16.row.col.f32.bf16.bf16.f32 "
        "{%0,%1,%2,%3}, {%4,%5,%6,%7}, {%8,%9}, {%0,%1,%2,%3};"
        : "+f"(c[0]), "+f"(c[1]), "+f"(c[2]), "+f"(c[3])
        : "r"(a[0]), "r"(a[1]), "r"(a[2]), "r"(a[3]), "r"(b0), "r"(b1));
}

// ---------------- prep: split x into bf16 hi/lo -----------------------------
__global__ __launch_bounds__(256) void splitX_kernel(
    const float* __restrict__ X,
    __nv_bfloat16* __restrict__ Hi, __nv_bfloat16* __restrict__ Lo)
{
    int i = blockIdx.x * 256 + threadIdx.x;  // float4 index, exact cover
    float4 v = ((const float4*)X)[i];
    __nv_bfloat16 h0 = __float2bfloat16(v.x), h1 = __float2bfloat16(v.y);
    __nv_bfloat16 h2 = __float2bfloat16(v.z), h3 = __float2bfloat16(v.w);
    __nv_bfloat162 hA = __halves2bfloat162(h0, h1);
    __nv_bfloat162 hB = __halves2bfloat162(h2, h3);
    __nv_bfloat162 lA = __halves2bfloat162(
        __float2bfloat16(v.x - __bfloat162float(h0)),
        __float2bfloat16(v.y - __bfloat162float(h1)));
    __nv_bfloat162 lB = __halves2bfloat162(
        __float2bfloat16(v.z - __bfloat162float(h2)),
        __float2bfloat16(v.w - __bfloat162float(h3)));
    ((__nv_bfloat162*)Hi)[i * 2]     = hA;
    ((__nv_bfloat162*)Hi)[i * 2 + 1] = hB;
    ((__nv_bfloat162*)Lo)[i * 2]     = lA;
    ((__nv_bfloat162*)Lo)[i * 2 + 1] = lB;
}

// ---------------- prep: transpose W[k][n] -> [n][k] + split -----------------
__global__ void splitW_kernel(const float* __restrict__ W, int ldw,
                              __nv_bfloat16* __restrict__ Ohi,
                              __nv_bfloat16* __restrict__ Olo)
{
    __shared__ float t[32][33];
    int tx = threadIdx.x, ty = threadIdx.y;
    int n0 = blockIdx.x * 32, k0 = blockIdx.y * 32;
#pragma unroll
    for (int p = 0; p < 4; p++)
        t[ty + 8 * p][tx] = W[(size_t)(k0 + ty + 8 * p) * ldw + n0 + tx];
    __syncthreads();
#pragma unroll
    for (int p = 0; p < 4; p++) {
        float v = t[tx][ty + 8 * p];
        __nv_bfloat16 h = __float2bfloat16(v);
        size_t o = (size_t)(n0 + ty + 8 * p) * 1024 + k0 + tx;
        Ohi[o] = h;
        Olo[o] = __float2bfloat16(v - __bfloat162float(h));
    }
}

// ---------------- tensor-core GEMM via mma.sync (bf16 3-split) --------------
// C[4096,1024] = A @ B^T + bias, A hi/lo [4096][1024] k-major,
// B hi/lo [1024(n)][1024(k)] k-major. Tile 128x128, BK=64, 8 warps (2x4),
// warp tile 64x32. cp.async double-buffered smem, ldmatrix fragments.
#define ROWB 144   // padded row stride in bytes (72 bf16) — conflict-free ldsm
#define MATB (128 * ROWB)      // 18432 bytes per matrix
#define STAGEB (4 * MATB)      // Ahi,Alo,Bhi,Blo per stage

__global__ __launch_bounds__(256) void gemm_mma(
    const __nv_bfloat16* __restrict__ Ahi, const __nv_bfloat16* __restrict__ Alo,
    const __nv_bfloat16* __restrict__ Bhi, const __nv_bfloat16* __restrict__ Blo,
    const float* __restrict__ bias, float* __restrict__ C)
{
    extern __shared__ char smem[];
    const uint32_t sb = smem_u32(smem);
    const int tid = threadIdx.x;
    const int wid = tid >> 5;
    const int lane = tid & 31;
    const int wm = wid >> 2;        // 0..1 (64 rows each)
    const int wn = wid & 3;         // 0..3 (32 cols each)
    const int m0 = blockIdx.y * 128, n0 = blockIdx.x * 128;

    const char* srcs[4] = {(const char*)Ahi, (const char*)Alo,
                           (const char*)Bhi, (const char*)Blo};
    const int rowbase[4] = {m0, m0, n0, n0};

    // loader indices: 1024 16B units per matrix -> 4 per thread
    const int lrow = tid >> 3;        // *stride 32 below covers 128 rows
    const int lkc = tid & 7;          // 16B unit along k

    // fragment smem offsets (within a matrix)
    const uint32_t a_off = (uint32_t)((wm * 64 + (lane & 15)) * ROWB + (lane >> 4) * 16);
    const uint32_t b_off = (uint32_t)((wn * 32 + (lane & 15)) * ROWB + (lane >> 4) * 16);

    float acc[4][4][4];
#pragma unroll
    for (int i = 0; i < 4; i++)
#pragma unroll
        for (int j = 0; j < 4; j++)
#pragma unroll
            for (int r = 0; r < 4; r++) acc[i][j][r] = 0.0f;

    // prologue: load chunk 0 into stage 0
#pragma unroll
    for (int ts = 0; ts < 4; ts++) {
        const char* src = srcs[ts];
        const int rb = rowbase[ts];
#pragma unroll
        for (int q = 0; q < 4; q++) {
            int row = lrow + q * 32;
            cp_async16(sb + ts * MATB + row * ROWB + lkc * 16,
                       src + (size_t)(rb + row) * 2048 + lkc * 16);
        }
    }
    cp_commit();

    for (int c = 0; c < 16; c++) {
        const uint32_t st = (uint32_t)(c & 1) * STAGEB;
        if (c + 1 < 16) {
            const uint32_t st2 = (uint32_t)((c + 1) & 1) * STAGEB;
#pragma unroll
            for (int ts = 0; ts < 4; ts++) {
                const char* src = srcs[ts];
                const int rb = rowbase[ts];
#pragma unroll
                for (int q = 0; q < 4; q++) {
                    int row = lrow + q * 32;
                    cp_async16(st2 + sb + ts * MATB + row * ROWB + lkc * 16,
                               src + (size_t)(rb + row) * 2048 + (c + 1) * 128 + lkc * 16);
                }
            }
            cp_commit();
            cp_wait1();
        } else {
            cp_wait0();
        }
        __syncthreads();

#pragma unroll
        for (int kk = 0; kk < 4; kk++) {
            // B fragments: two n16 blocks, hi & lo
            uint32_t bh[2][4], bl[2][4];
#pragma unroll
            for (int p = 0; p < 2; p++) {
                uint32_t addr = st + sb + 2 * MATB + b_off + p * 16 * ROWB + kk * 32;
                ldsm4(bh[p][0], bh[p][1], bh[p][2], bh[p][3], addr);
                ldsm4(bl[p][0], bl[p][1], bl[p][2], bl[p][3], addr + MATB);
            }
#pragma unroll
            for (int mf = 0; mf < 4; mf++) {
                uint32_t ah[4], al[4];
                uint32_t addr = st + sb + a_off + mf * 16 * ROWB + kk * 32;
                ldsm4(ah[0], ah[1], ah[2], ah[3], addr);
                ldsm4(al[0], al[1], al[2], al[3], addr + MATB);
#pragma unroll
                for (int nf = 0; nf < 4; nf++) {
                    const int p = nf >> 1, hh = nf & 1;
                    mma_bf16(acc[mf][nf], ah, bh[p][hh], bh[p][2 + hh]);
                    mma_bf16(acc[mf][nf], ah, bl[p][hh], bl[p][2 + hh]);
                    mma_bf16(acc[mf][nf], al, bh[p][hh], bh[p][2 + hh]);
                }
            }
        }
        __syncthreads();
    }

    // epilogue: c0,c1 -> row g=lane>>2 cols (lane&3)*2; c2,c3 -> row g+8
#pragma unroll
    for (int nf = 0; nf < 4; nf++) {
        int n = n0 + wn * 32 + nf * 8 + (lane & 3) * 2;
        float2 bv = *(const float2*)(bias + n);
#pragma unroll
        for (int mf = 0; mf < 4; mf++) {
            int m = m0 + wm * 64 + mf * 16 + (lane >> 2);
            float2 o0 = {acc[mf][nf][0] + bv.x, acc[mf][nf][1] + bv.y};
            float2 o1 = {acc[mf][nf][2] + bv.x, acc[mf][nf][3] + bv.y};
            *(float2*)(C + (size_t)m * 1024 + n) = o0;
            *(float2*)(C + (size_t)(m + 8) * 1024 + n) = o1;
        }
    }
}

// ---------------- fused flash attention (f32x2) -----------------------------
// Outputs directly as bf16 hi/lo split for the projection GEMM.
__global__ __launch_bounds__(256) void attn_kernel(
    const float* __restrict__ K,
    __nv_bfloat16* __restrict__ OutHi, __nv_bfloat16* __restrict__ OutLo)
{
    extern __shared__ float sm[];
    float* Qt = sm;                       // 64 * 66
    float* Ks = sm + 64 * 66;             // 128 * 66
    float* Kd = sm + 64 * 66 + 128 * 66;  // 64 * 130
    float* Pt = Kd + 64 * 130;            // 64 * 130
    const ull* Qt64 = (const ull*)Qt;
    const ull* Ks64 = (const ull*)Ks;
    const ull* Kd64 = (const ull*)Kd;
    const ull* Pt64 = (const ull*)Pt;

    const int tid = threadIdx.x;
    const int tx = tid & 15;
    const int ty = tid >> 4;
    const int b = blockIdx.y >> 4;
    const int h = blockIdx.y & 15;
    const int q0 = blockIdx.x * 64;

    const float* Kb = K + (size_t)b * 2048 * 1024 + h * 64;
    const float QSCALE = 0.125f * 1.4426950408889634f;

#pragma unroll
    for (int p = 0; p < 16; p++) {
        int i = tid + p * 256;
        int q = i >> 6, d = i & 63;
        Qt[q * 66 + d] = Kb[(size_t)(q0 + q) * 1024 + d] * QSCALE;
    }

    float m_i[4], l_i[4];
    ull O2[4][4];
#pragma unroll
    for (int i = 0; i < 4; i++) {
        m_i[i] = -1e30f;
        l_i[i] = 0.0f;
#pragma unroll
        for (int d = 0; d < 4; d++) O2[i][d] = 0ull;
    }

    for (int k0 = 0; k0 < 2048; k0 += 128) {
        __syncthreads();
#pragma unroll
        for (int p = 0; p < 32; p++) {
            int i = tid + p * 256;
            int j = i >> 6, d = i & 63;
            float v = Kb[(size_t)(k0 + j) * 1024 + d];
            Ks[j * 66 + d] = v;
            Kd[d * 130 + j] = v;
        }
        __syncthreads();

        ull s2[4][8];
#pragma unroll
        for (int i = 0; i < 4; i++)
#pragma unroll
            for (int j = 0; j < 8; j++) s2[i][j] = 0ull;

#pragma unroll 8
        for (int dd = 0; dd < 32; dd++) {
            ull a[4], bb[8];
#pragma unroll
            for (int i = 0; i < 4; i++) a[i] = Qt64[(ty + 16 * i) * 33 + dd];
#pragma unroll
            for (int j = 0; j < 8; j++) bb[j] = Ks64[(tx + 16 * j) * 33 + dd];
#pragma unroll
            for (int i = 0; i < 4; i++)
#pragma unroll
                for (int j = 0; j < 8; j++) s2[i][j] = fma2(a[i], bb[j], s2[i][j]);
        }

#pragma unroll
        for (int i = 0; i < 4; i++) {
            float s[8];
            float mx = -1e30f;
#pragma unroll
            for (int j = 0; j < 8; j++) {
                float2 v = unpack2(s2[i][j]);
                s[j] = v.x + v.y;
                mx = fmaxf(mx, s[j]);
            }
            mx = fmaxf(mx, __shfl_xor_sync(0xffffffffu, mx, 1));
            mx = fmaxf(mx, __shfl_xor_sync(0xffffffffu, mx, 2));
            mx = fmaxf(mx, __shfl_xor_sync(0xffffffffu, mx, 4));
            mx = fmaxf(mx, __shfl_xor_sync(0xffffffffu, mx, 8));
            float mnew = fmaxf(m_i[i], mx);
            float corr = fast_exp2(m_i[i] - mnew);
            float rs = 0.0f;
#pragma unroll
            for (int j = 0; j < 8; j++) {
                s[j] = fast_exp2(s[j] - mnew);
                rs += s[j];
            }
            rs += __shfl_xor_sync(0xffffffffu, rs, 1);
            rs += __shfl_xor_sync(0xffffffffu, rs, 2);
            rs += __shfl_xor_sync(0xffffffffu, rs, 4);
            rs += __shfl_xor_sync(0xffffffffu, rs, 8);
            l_i[i] = l_i[i] * corr + rs;
            m_i[i] = mnew;
            ull c2 = pack2(corr, corr);
#pragma unroll
            for (int d = 0; d < 4; d++) O2[i][d] = mul2(O2[i][d], c2);
            float* prow = Pt + (ty + 16 * i) * 130;
#pragma unroll
            for (int j = 0; j < 8; j++) prow[tx + 16 * j] = s[j];
        }
        __syncthreads();

#pragma unroll 8
        for (int jj = 0; jj < 64; jj++) {
            ull a[4], bb[4];
#pragma unroll
            for (int i = 0; i < 4; i++) a[i] = Pt64[(ty + 16 * i) * 65 + jj];
#pragma unroll
            for (int d = 0; d < 4; d++) bb[d] = Kd64[(tx + 16 * d) * 65 + jj];
#pragma unroll
            for (int i = 0; i < 4; i++)
#pragma unroll
                for (int d = 0; d < 4; d++) O2[i][d] = fma2(a[i], bb[d], O2[i][d]);
        }
    }

#pragma unroll
    for (int i = 0; i < 4; i++) {
        float inv = 1.0f / l_i[i];
        int q = q0 + ty + 16 * i;
#pragma unroll
        for (int d = 0; d < 4; d++) {
            float2 v = unpack2(O2[i][d]);
            float val = (v.x + v.y) * inv;
            size_t idx = ((size_t)b * 2048 + q) * 1024 + h * 64 + tx + 16 * d;
            __nv_bfloat16 hh = __float2bfloat16(val);
            OutHi[idx] = hh;
            OutLo[idx] = __float2bfloat16(val - __bfloat162float(hh));
        }
    }
}

// ---------------------------------------------------------------------------
extern "C" void kernel_launch(void* const* d_in, const int* in_sizes, int n_in,
                              void* d_out, int out_size) {
    const float* x      = (const float*)d_in[0];  // (2, 2048, 1024)
    const float* W_attn = (const float*)d_in[1];  // (1024, 3072)
    const float* b_attn = (const float*)d_in[2];  // (3072,)
    const float* W_proj = (const float*)d_in[3];  // (1024, 1024)
    const float* b_proj = (const float*)d_in[4];  // (1024,)
    float* out = (float*)d_out;                   // (2, 2048, 1024)

    float* gK;
    __nv_bfloat16 *xs_hi, *xs_lo, *att_hi, *att_lo, *wk_hi, *wk_lo, *wp_hi, *wp_lo;
    cudaGetSymbolAddress((void**)&gK, g_K);
    cudaGetSymbolAddress((void**)&xs_hi, g_xs_hi);
    cudaGetSymbolAddress((void**)&xs_lo, g_xs_lo);
    cudaGetSymbolAddress((void**)&att_hi, g_att_hi);
    cudaGetSymbolAddress((void**)&att_lo, g_att_lo);
    cudaGetSymbolAddress((void**)&wk_hi, g_wk_hi);
    cudaGetSymbolAddress((void**)&wk_lo, g_wk_lo);
    cudaGetSymbolAddress((void**)&wp_hi, g_wp_hi);
    cudaGetSymbolAddress((void**)&wp_lo, g_wp_lo);

    const int GEMM_SMEM = 2 * STAGEB;  // 147456
    cudaFuncSetAttribute(gemm_mma,
                         cudaFuncAttributeMaxDynamicSharedMemorySize, GEMM_SMEM);
    const int ATTN_SMEM = (64 * 66 + 128 * 66 + 64 * 130 + 64 * 130) * (int)sizeof(float);
    cudaFuncSetAttribute(attn_kernel,
                         cudaFuncAttributeMaxDynamicSharedMemorySize, ATTN_SMEM);

    // Prep: bf16 splits
    splitX_kernel<<<4096, 256>>>(x, xs_hi, xs_lo);
    splitW_kernel<<<dim3(32, 32), dim3(32, 8)>>>(W_attn + 1024, 3072, wk_hi, wk_lo);
    splitW_kernel<<<dim3(32, 32), dim3(32, 8)>>>(W_proj, 1024, wp_hi, wp_lo);

    // Stage 1: K = x @ W_attn[:, D:2D] + b_attn[D:2D]  (tensor cores, 3-split)
    gemm_mma<<<dim3(8, 32), 256, GEMM_SMEM>>>(xs_hi, xs_lo, wk_hi, wk_lo,
                                              b_attn + 1024, gK);

    // Stage 2: fused flash attention; writes bf16 hi/lo split output.
    attn_kernel<<<dim3(32, 32), 256, ATTN_SMEM>>>(gK, att_hi, att_lo);

    // Stage 3: out = att @ W_proj + b_proj  (tensor cores, 3-split)
    gemm_mma<<<dim3(8, 32), 256, GEMM_SMEM>>>(att_hi, att_lo, wp_hi, wp_lo,
                                              b_proj, out);
}

// round 6
// speedup vs baseline: 3.1806x; 2.0904x over previous
#include <cuda_runtime.h>
#include <cuda_bf16.h>
#include <cstdint>

typedef unsigned long long ull;

// ---------------- scratch (__device__ globals; no allocation allowed) -------
__device__ float g_K[4096 * 1024];                    // stage-1 output (fp32)
__device__ __nv_bfloat16 g_xs_hi[4096 * 1024];        // split of x
__device__ __nv_bfloat16 g_xs_lo[4096 * 1024];
__device__ __nv_bfloat16 g_att_hi[4096 * 1024];       // split of attention out
__device__ __nv_bfloat16 g_att_lo[4096 * 1024];
__device__ __nv_bfloat16 g_wk_hi[1024 * 1024];        // W_attn K-slice, [n][k]
__device__ __nv_bfloat16 g_wk_lo[1024 * 1024];
__device__ __nv_bfloat16 g_wp_hi[1024 * 1024];        // W_proj, [n][k]
__device__ __nv_bfloat16 g_wp_lo[1024 * 1024];

// ---------------- PTX helpers (all compute_103-safe) ------------------------
__device__ __forceinline__ float fast_exp2(float x) {
    float y; asm("ex2.approx.ftz.f32 %0, %1;" : "=f"(y) : "f"(x)); return y;
}
__device__ __forceinline__ uint32_t smem_u32(const void* p) {
    uint32_t a;
    asm("{ .reg .u64 t; cvta.to.shared.u64 t, %1; cvt.u32.u64 %0, t; }" : "=r"(a) : "l"(p));
    return a;
}
__device__ __forceinline__ void cp_async16(uint32_t dst, const void* src) {
    asm volatile("cp.async.cg.shared.global [%0], [%1], 16;" :: "r"(dst), "l"(src));
}
__device__ __forceinline__ void cp_commit() {
    asm volatile("cp.async.commit_group;" ::: "memory");
}
__device__ __forceinline__ void cp_wait1() {
    asm volatile("cp.async.wait_group 1;" ::: "memory");
}
__device__ __forceinline__ void cp_wait0() {
    asm volatile("cp.async.wait_group 0;" ::: "memory");
}
__device__ __forceinline__ void ldsm4(uint32_t& r0, uint32_t& r1, uint32_t& r2,
                                      uint32_t& r3, uint32_t addr) {
    asm volatile("ldmatrix.sync.aligned.m8n8.x4.shared.b16 {%0,%1,%2,%3}, [%4];"
                 : "=r"(r0), "=r"(r1), "=r"(r2), "=r"(r3) : "r"(addr));
}
__device__ __forceinline__ void ldsm4t(uint32_t& r0, uint32_t& r1, uint32_t& r2,
                                       uint32_t& r3, uint32_t addr) {
    asm volatile("ldmatrix.sync.aligned.m8n8.x4.trans.shared.b16 {%0,%1,%2,%3}, [%4];"
                 : "=r"(r0), "=r"(r1), "=r"(r2), "=r"(r3) : "r"(addr));
}
__device__ __forceinline__ void mma_bf16(float* c, const uint32_t* a,
                                         uint32_t b0, uint32_t b1) {
    asm volatile(
        "mma.sync.aligned.m16n8k16.row.col.f32.bf16.bf16.f32 "
        "{%0,%1,%2,%3}, {%4,%5,%6,%7}, {%8,%9}, {%0,%1,%2,%3};"
        : "+f"(c[0]), "+f"(c[1]), "+f"(c[2]), "+f"(c[3])
        : "r"(a[0]), "r"(a[1]), "r"(a[2]), "r"(a[3]), "r"(b0), "r"(b1));
}
__device__ __forceinline__ uint32_t pack_bf16x2(float lo, float hi) {
    __nv_bfloat162 r = __float22bfloat162_rn(make_float2(lo, hi));
    return *(uint32_t*)&r;
}

// ---------------- prep: split x into bf16 hi/lo -----------------------------
__global__ __launch_bounds__(256) void splitX_kernel(
    const float* __restrict__ X,
    __nv_bfloat16* __restrict__ Hi, __nv_bfloat16* __restrict__ Lo)
{
    int i = blockIdx.x * 256 + threadIdx.x;  // float4 index, exact cover
    float4 v = ((const float4*)X)[i];
    __nv_bfloat16 h0 = __float2bfloat16(v.x), h1 = __float2bfloat16(v.y);
    __nv_bfloat16 h2 = __float2bfloat16(v.z), h3 = __float2bfloat16(v.w);
    __nv_bfloat162 hA = __halves2bfloat162(h0, h1);
    __nv_bfloat162 hB = __halves2bfloat162(h2, h3);
    __nv_bfloat162 lA = __halves2bfloat162(
        __float2bfloat16(v.x - __bfloat162float(h0)),
        __float2bfloat16(v.y - __bfloat162float(h1)));
    __nv_bfloat162 lB = __halves2bfloat162(
        __float2bfloat16(v.z - __bfloat162float(h2)),
        __float2bfloat16(v.w - __bfloat162float(h3)));
    ((__nv_bfloat162*)Hi)[i * 2]     = hA;
    ((__nv_bfloat162*)Hi)[i * 2 + 1] = hB;
    ((__nv_bfloat162*)Lo)[i * 2]     = lA;
    ((__nv_bfloat162*)Lo)[i * 2 + 1] = lB;
}

// ---------------- prep: transpose W[k][n] -> [n][k] + split -----------------
__global__ void splitW_kernel(const float* __restrict__ W, int ldw,
                              __nv_bfloat16* __restrict__ Ohi,
                              __nv_bfloat16* __restrict__ Olo)
{
    __shared__ float t[32][33];
    int tx = threadIdx.x, ty = threadIdx.y;
    int n0 = blockIdx.x * 32, k0 = blockIdx.y * 32;
#pragma unroll
    for (int p = 0; p < 4; p++)
        t[ty + 8 * p][tx] = W[(size_t)(k0 + ty + 8 * p) * ldw + n0 + tx];
    __syncthreads();
#pragma unroll
    for (int p = 0; p < 4; p++) {
        float v = t[tx][ty + 8 * p];
        __nv_bfloat16 h = __float2bfloat16(v);
        size_t o = (size_t)(n0 + ty + 8 * p) * 1024 + k0 + tx;
        Ohi[o] = h;
        Olo[o] = __float2bfloat16(v - __bfloat162float(h));
    }
}

// ---------------- tensor-core GEMM via mma.sync (bf16 3-split) --------------
#define ROWB 144
#define MATB (128 * ROWB)
#define STAGEB (4 * MATB)

__global__ __launch_bounds__(256) void gemm_mma(
    const __nv_bfloat16* __restrict__ Ahi, const __nv_bfloat16* __restrict__ Alo,
    const __nv_bfloat16* __restrict__ Bhi, const __nv_bfloat16* __restrict__ Blo,
    const float* __restrict__ bias, float* __restrict__ C)
{
    extern __shared__ char smem[];
    const uint32_t sb = smem_u32(smem);
    const int tid = threadIdx.x;
    const int wid = tid >> 5;
    const int lane = tid & 31;
    const int wm = wid >> 2;
    const int wn = wid & 3;
    const int m0 = blockIdx.y * 128, n0 = blockIdx.x * 128;

    const char* srcs[4] = {(const char*)Ahi, (const char*)Alo,
                           (const char*)Bhi, (const char*)Blo};
    const int rowbase[4] = {m0, m0, n0, n0};

    const int lrow = tid >> 3;
    const int lkc = tid & 7;

    const uint32_t a_off = (uint32_t)((wm * 64 + (lane & 15)) * ROWB + (lane >> 4) * 16);
    const uint32_t b_off = (uint32_t)((wn * 32 + (lane & 15)) * ROWB + (lane >> 4) * 16);

    float acc[4][4][4];
#pragma unroll
    for (int i = 0; i < 4; i++)
#pragma unroll
        for (int j = 0; j < 4; j++)
#pragma unroll
            for (int r = 0; r < 4; r++) acc[i][j][r] = 0.0f;

#pragma unroll
    for (int ts = 0; ts < 4; ts++) {
        const char* src = srcs[ts];
        const int rb = rowbase[ts];
#pragma unroll
        for (int q = 0; q < 4; q++) {
            int row = lrow + q * 32;
            cp_async16(sb + ts * MATB + row * ROWB + lkc * 16,
                       src + (size_t)(rb + row) * 2048 + lkc * 16);
        }
    }
    cp_commit();

    for (int c = 0; c < 16; c++) {
        const uint32_t st = (uint32_t)(c & 1) * STAGEB;
        if (c + 1 < 16) {
            const uint32_t st2 = (uint32_t)((c + 1) & 1) * STAGEB;
#pragma unroll
            for (int ts = 0; ts < 4; ts++) {
                const char* src = srcs[ts];
                const int rb = rowbase[ts];
#pragma unroll
                for (int q = 0; q < 4; q++) {
                    int row = lrow + q * 32;
                    cp_async16(st2 + sb + ts * MATB + row * ROWB + lkc * 16,
                               src + (size_t)(rb + row) * 2048 + (c + 1) * 128 + lkc * 16);
                }
            }
            cp_commit();
            cp_wait1();
        } else {
            cp_wait0();
        }
        __syncthreads();

#pragma unroll
        for (int kk = 0; kk < 4; kk++) {
            uint32_t bh[2][4], bl[2][4];
#pragma unroll
            for (int p = 0; p < 2; p++) {
                uint32_t addr = st + sb + 2 * MATB + b_off + p * 16 * ROWB + kk * 32;
                ldsm4(bh[p][0], bh[p][1], bh[p][2], bh[p][3], addr);
                ldsm4(bl[p][0], bl[p][1], bl[p][2], bl[p][3], addr + MATB);
            }
#pragma unroll
            for (int mf = 0; mf < 4; mf++) {
                uint32_t ah[4], al[4];
                uint32_t addr = st + sb + a_off + mf * 16 * ROWB + kk * 32;
                ldsm4(ah[0], ah[1], ah[2], ah[3], addr);
                ldsm4(al[0], al[1], al[2], al[3], addr + MATB);
#pragma unroll
                for (int nf = 0; nf < 4; nf++) {
                    const int p = nf >> 1, hh = nf & 1;
                    mma_bf16(acc[mf][nf], ah, bh[p][hh], bh[p][2 + hh]);
                    mma_bf16(acc[mf][nf], ah, bl[p][hh], bl[p][2 + hh]);
                    mma_bf16(acc[mf][nf], al, bh[p][hh], bh[p][2 + hh]);
                }
            }
        }
        __syncthreads();
    }

#pragma unroll
    for (int nf = 0; nf < 4; nf++) {
        int n = n0 + wn * 32 + nf * 8 + (lane & 3) * 2;
        float2 bv = *(const float2*)(bias + n);
#pragma unroll
        for (int mf = 0; mf < 4; mf++) {
            int m = m0 + wm * 64 + mf * 16 + (lane >> 2);
            float2 o0 = {acc[mf][nf][0] + bv.x, acc[mf][nf][1] + bv.y};
            float2 o1 = {acc[mf][nf][2] + bv.x, acc[mf][nf][3] + bv.y};
            *(float2*)(C + (size_t)m * 1024 + n) = o0;
            *(float2*)(C + (size_t)(m + 8) * 1024 + n) = o1;
        }
    }
}

// ---------------- FA2-style attention on tensor cores -----------------------
// Per CTA: one (b,h), 128 query rows; 8 warps x 16 rows. Key tiles of 128.
// S = Q K^T (3-split), online softmax in fragments, O += P V (3-split with P
// hi/lo built in registers, V = K tile via ldmatrix.trans).
// smem: Qhi/Qlo [128][64] bf16 (144B rows), Khi/Klo [128][64] bf16.
#define AQ_HI 0
#define AQ_LO 18432
#define AK_HI 36864
#define AK_LO 55296
#define ATTN_SMEM_B 73728

__global__ __launch_bounds__(256) void attn_mma(
    const float* __restrict__ K,
    __nv_bfloat16* __restrict__ OutHi, __nv_bfloat16* __restrict__ OutLo)
{
    extern __shared__ char smem[];
    const uint32_t sb = smem_u32(smem);
    const int tid = threadIdx.x;
    const int wid = tid >> 5;
    const int lane = tid & 31;
    const int g = lane >> 2;          // row within 8
    const int tq = lane & 3;          // col pair selector
    const int b = blockIdx.y >> 4;
    const int h = blockIdx.y & 15;
    const int q0 = blockIdx.x * 128;

    const float* Kb = K + (size_t)b * 2048 * 1024 + h * 64;
    const float QSCALE = 0.125f * 1.4426950408889634f;

    // ---- load Q tile (scaled) into Qhi/Qlo ----
#pragma unroll
    for (int p = 0; p < 8; p++) {
        int i = tid + p * 256;
        int q = i >> 4, dc = i & 15;
        float4 v = *(const float4*)(Kb + (size_t)(q0 + q) * 1024 + dc * 4);
        v.x *= QSCALE; v.y *= QSCALE; v.z *= QSCALE; v.w *= QSCALE;
        __nv_bfloat16 h0 = __float2bfloat16(v.x), h1 = __float2bfloat16(v.y);
        __nv_bfloat16 h2 = __float2bfloat16(v.z), h3 = __float2bfloat16(v.w);
        char* base = smem + q * 144 + dc * 8;
        *(__nv_bfloat162*)(base + AQ_HI)     = __halves2bfloat162(h0, h1);
        *(__nv_bfloat162*)(base + AQ_HI + 4) = __halves2bfloat162(h2, h3);
        *(__nv_bfloat162*)(base + AQ_LO)     = __halves2bfloat162(
            __float2bfloat16(v.x - __bfloat162float(h0)),
            __float2bfloat16(v.y - __bfloat162float(h1)));
        *(__nv_bfloat162*)(base + AQ_LO + 4) = __halves2bfloat162(
            __float2bfloat16(v.z - __bfloat162float(h2)),
            __float2bfloat16(v.w - __bfloat162float(h3)));
    }

    float m0 = -1e30f, m1 = -1e30f, l0 = 0.0f, l1 = 0.0f;
    float o[8][4];
#pragma unroll
    for (int nf = 0; nf < 8; nf++)
#pragma unroll
        for (int r = 0; r < 4; r++) o[nf][r] = 0.0f;

    const uint32_t qa_off = (uint32_t)((wid * 16 + (lane & 15)) * 144 + (lane >> 4) * 16);
    const uint32_t kb_row = (uint32_t)((lane & 15) * 144 + (lane >> 4) * 16);
    const uint32_t vb_row = (uint32_t)((lane & 15) * 144 + (lane >> 4) * 16);

    for (int kt = 0; kt < 16; kt++) {
        __syncthreads();
        // ---- load K tile into Khi/Klo (unscaled) ----
        const int j0 = kt * 128;
#pragma unroll
        for (int p = 0; p < 8; p++) {
            int i = tid + p * 256;
            int j = i >> 4, dc = i & 15;
            float4 v = *(const float4*)(Kb + (size_t)(j0 + j) * 1024 + dc * 4);
            __nv_bfloat16 h0 = __float2bfloat16(v.x), h1 = __float2bfloat16(v.y);
            __nv_bfloat16 h2 = __float2bfloat16(v.z), h3 = __float2bfloat16(v.w);
            char* base = smem + j * 144 + dc * 8;
            *(__nv_bfloat162*)(base + AK_HI)     = __halves2bfloat162(h0, h1);
            *(__nv_bfloat162*)(base + AK_HI + 4) = __halves2bfloat162(h2, h3);
            *(__nv_bfloat162*)(base + AK_LO)     = __halves2bfloat162(
                __float2bfloat16(v.x - __bfloat162float(h0)),
                __float2bfloat16(v.y - __bfloat162float(h1)));
            *(__nv_bfloat162*)(base + AK_LO + 4) = __halves2bfloat162(
                __float2bfloat16(v.z - __bfloat162float(h2)),
                __float2bfloat16(v.w - __bfloat162float(h3)));
        }
        __syncthreads();

        // ---- S = Q K^T over this tile: s[16 nf][4] ----
        float s[16][4];
#pragma unroll
        for (int nf = 0; nf < 16; nf++)
#pragma unroll
            for (int r = 0; r < 4; r++) s[nf][r] = 0.0f;

#pragma unroll
        for (int kk = 0; kk < 4; kk++) {
            uint32_t qh[4], ql[4];
            ldsm4(qh[0], qh[1], qh[2], qh[3], sb + AQ_HI + qa_off + kk * 32);
            ldsm4(ql[0], ql[1], ql[2], ql[3], sb + AQ_LO + qa_off + kk * 32);
#pragma unroll
            for (int nb = 0; nb < 8; nb++) {
                uint32_t kh[4], kl[4];
                uint32_t addr = sb + kb_row + (uint32_t)(nb * 16 * 144) + kk * 32;
                ldsm4(kh[0], kh[1], kh[2], kh[3], addr + AK_HI);
                ldsm4(kl[0], kl[1], kl[2], kl[3], addr + AK_LO);
#pragma unroll
                for (int hh = 0; hh < 2; hh++) {
                    mma_bf16(s[2 * nb + hh], qh, kh[hh], kh[2 + hh]);
                    mma_bf16(s[2 * nb + hh], qh, kl[hh], kl[2 + hh]);
                    mma_bf16(s[2 * nb + hh], ql, kh[hh], kh[2 + hh]);
                }
            }
        }

        // ---- online softmax (rows g and g+8 of this warp's 16) ----
        float mx0 = -1e30f, mx1 = -1e30f;
#pragma unroll
        for (int nf = 0; nf < 16; nf++) {
            mx0 = fmaxf(mx0, fmaxf(s[nf][0], s[nf][1]));
            mx1 = fmaxf(mx1, fmaxf(s[nf][2], s[nf][3]));
        }
        mx0 = fmaxf(mx0, __shfl_xor_sync(0xffffffffu, mx0, 1));
        mx0 = fmaxf(mx0, __shfl_xor_sync(0xffffffffu, mx0, 2));
        mx1 = fmaxf(mx1, __shfl_xor_sync(0xffffffffu, mx1, 1));
        mx1 = fmaxf(mx1, __shfl_xor_sync(0xffffffffu, mx1, 2));
        float mn0 = fmaxf(m0, mx0), mn1 = fmaxf(m1, mx1);
        float c0 = fast_exp2(m0 - mn0), c1 = fast_exp2(m1 - mn1);
        m0 = mn0; m1 = mn1;
        l0 *= c0; l1 *= c1;
#pragma unroll
        for (int nf = 0; nf < 8; nf++) {
            o[nf][0] *= c0; o[nf][1] *= c0;
            o[nf][2] *= c1; o[nf][3] *= c1;
        }
        float rs0 = 0.0f, rs1 = 0.0f;
#pragma unroll
        for (int nf = 0; nf < 16; nf++) {
            s[nf][0] = fast_exp2(s[nf][0] - mn0);
            s[nf][1] = fast_exp2(s[nf][1] - mn0);
            s[nf][2] = fast_exp2(s[nf][2] - mn1);
            s[nf][3] = fast_exp2(s[nf][3] - mn1);
            rs0 += s[nf][0] + s[nf][1];
            rs1 += s[nf][2] + s[nf][3];
        }
        rs0 += __shfl_xor_sync(0xffffffffu, rs0, 1);
        rs0 += __shfl_xor_sync(0xffffffffu, rs0, 2);
        rs1 += __shfl_xor_sync(0xffffffffu, rs1, 1);
        rs1 += __shfl_xor_sync(0xffffffffu, rs1, 2);
        l0 += rs0; l1 += rs1;

        // ---- O += P V : P hi/lo fragments from registers, V via ldsm.trans ----
#pragma unroll
        for (int t = 0; t < 8; t++) {
            uint32_t ph[4], pl[4];
#pragma unroll
            for (int half = 0; half < 2; half++) {
                const int nf = 2 * t + half;
                float h00f = s[nf][0], h01f = s[nf][1];
                float h10f = s[nf][2], h11f = s[nf][3];
                uint32_t hi0 = pack_bf16x2(h00f, h01f);
                uint32_t hi1 = pack_bf16x2(h10f, h11f);
                __nv_bfloat162 hv0 = *(__nv_bfloat162*)&hi0;
                __nv_bfloat162 hv1 = *(__nv_bfloat162*)&hi1;
                uint32_t lo0 = pack_bf16x2(h00f - __bfloat162float(hv0.x),
                                           h01f - __bfloat162float(hv0.y));
                uint32_t lo1 = pack_bf16x2(h10f - __bfloat162float(hv1.x),
                                           h11f - __bfloat162float(hv1.y));
                ph[2 * half] = hi0; ph[2 * half + 1] = hi1;
                pl[2 * half] = lo0; pl[2 * half + 1] = lo1;
            }
#pragma unroll
            for (int nb = 0; nb < 4; nb++) {
                uint32_t vh[4], vl[4];
                uint32_t addr = sb + vb_row + (uint32_t)(t * 16 * 144) + nb * 32;
                ldsm4t(vh[0], vh[1], vh[2], vh[3], addr + AK_HI);
                ldsm4t(vl[0], vl[1], vl[2], vl[3], addr + AK_LO);
#pragma unroll
                for (int hh = 0; hh < 2; hh++) {
                    mma_bf16(o[2 * nb + hh], ph, vh[2 * hh], vh[2 * hh + 1]);
                    mma_bf16(o[2 * nb + hh], pl, vh[2 * hh], vh[2 * hh + 1]);
                    mma_bf16(o[2 * nb + hh], ph, vl[2 * hh], vl[2 * hh + 1]);
                }
            }
        }
    }

    // ---- epilogue: normalize and write bf16 hi/lo split ----
    float inv0 = 1.0f / l0, inv1 = 1.0f / l1;
    int mr0 = q0 + wid * 16 + g;
#pragma unroll
    for (int nf = 0; nf < 8; nf++) {
        int d = h * 64 + nf * 8 + tq * 2;
        size_t i0 = ((size_t)b * 2048 + mr0) * 1024 + d;
        size_t i1 = i0 + 8 * 1024;
        float v00 = o[nf][0] * inv0, v01 = o[nf][1] * inv0;
        float v10 = o[nf][2] * inv1, v11 = o[nf][3] * inv1;
        __nv_bfloat16 a0 = __float2bfloat16(v00), a1 = __float2bfloat16(v01);
        __nv_bfloat16 b0 = __float2bfloat16(v10), b1 = __float2bfloat16(v11);
        *(__nv_bfloat162*)(OutHi + i0) = __halves2bfloat162(a0, a1);
        *(__nv_bfloat162*)(OutHi + i1) = __halves2bfloat162(b0, b1);
        *(__nv_bfloat162*)(OutLo + i0) = __halves2bfloat162(
            __float2bfloat16(v00 - __bfloat162float(a0)),
            __float2bfloat16(v01 - __bfloat162float(a1)));
        *(__nv_bfloat162*)(OutLo + i1) = __halves2bfloat162(
            __float2bfloat16(v10 - __bfloat162float(b0)),
            __float2bfloat16(v11 - __bfloat162float(b1)));
    }
}

// ---------------------------------------------------------------------------
extern "C" void kernel_launch(void* const* d_in, const int* in_sizes, int n_in,
                              void* d_out, int out_size) {
    const float* x      = (const float*)d_in[0];  // (2, 2048, 1024)
    const float* W_attn = (const float*)d_in[1];  // (1024, 3072)
    const float* b_attn = (const float*)d_in[2];  // (3072,)
    const float* W_proj = (const float*)d_in[3];  // (1024, 1024)
    const float* b_proj = (const float*)d_in[4];  // (1024,)
    float* out = (float*)d_out;                   // (2, 2048, 1024)

    float* gK;
    __nv_bfloat16 *xs_hi, *xs_lo, *att_hi, *att_lo, *wk_hi, *wk_lo, *wp_hi, *wp_lo;
    cudaGetSymbolAddress((void**)&gK, g_K);
    cudaGetSymbolAddress((void**)&xs_hi, g_xs_hi);
    cudaGetSymbolAddress((void**)&xs_lo, g_xs_lo);
    cudaGetSymbolAddress((void**)&att_hi, g_att_hi);
    cudaGetSymbolAddress((void**)&att_lo, g_att_lo);
    cudaGetSymbolAddress((void**)&wk_hi, g_wk_hi);
    cudaGetSymbolAddress((void**)&wk_lo, g_wk_lo);
    cudaGetSymbolAddress((void**)&wp_hi, g_wp_hi);
    cudaGetSymbolAddress((void**)&wp_lo, g_wp_lo);

    const int GEMM_SMEM = 2 * STAGEB;  // 147456
    cudaFuncSetAttribute(gemm_mma,
                         cudaFuncAttributeMaxDynamicSharedMemorySize, GEMM_SMEM);
    cudaFuncSetAttribute(attn_mma,
                         cudaFuncAttributeMaxDynamicSharedMemorySize, ATTN_SMEM_B);

    // Prep: bf16 splits
    splitX_kernel<<<4096, 256>>>(x, xs_hi, xs_lo);
    splitW_kernel<<<dim3(32, 32), dim3(32, 8)>>>(W_attn + 1024, 3072, wk_hi, wk_lo);
    splitW_kernel<<<dim3(32, 32), dim3(32, 8)>>>(W_proj, 1024, wp_hi, wp_lo);

    // Stage 1: K = x @ W_attn[:, D:2D] + b_attn[D:2D]  (tensor cores, 3-split)
    gemm_mma<<<dim3(8, 32), 256, GEMM_SMEM>>>(xs_hi, xs_lo, wk_hi, wk_lo,
                                              b_attn + 1024, gK);

    // Stage 2: FA2-style attention on tensor cores; bf16 hi/lo split output.
    attn_mma<<<dim3(16, 32), 256, ATTN_SMEM_B>>>(gK, att_hi, att_lo);

    // Stage 3: out = att @ W_proj + b_proj  (tensor cores, 3-split)
    gemm_mma<<<dim3(8, 32), 256, GEMM_SMEM>>>(att_hi, att_lo, wp_hi, wp_lo,
                                              b_proj, out);
}